// round 14
// baseline (speedup 1.0000x reference)
#include <cuda_runtime.h>
#include <cuda_bf16.h>
#include <cuda_fp16.h>
#include <cstdint>

#define NUM_USERS 100000
#define NUM_ITEMS 50000
#define LATENT    64
#define N_EDGES   600000
#define BATCH     4096
#define N_NODES   (NUM_USERS + NUM_ITEMS)          // 150000
#define TOT_F     (N_NODES * LATENT)               // 9,600,000
#define USER_F    (NUM_USERS * LATENT)
#define N_DIR     (2 * N_EDGES)
#define N_PART    ((N_NODES + 255) / 256)          // 586

// ---------------- scratch (device globals) ----------------------------------
__device__ __half g_x0h[TOT_F];                    // fp16 inv-prescaled x0 (19.2 MB)
__device__ __half g_z[3 * TOT_F];                  // z_1..z_3 fp16 (57.6 MB)
__device__ int    g_degi  [N_NODES];               // zero at entry (reset by layer-1 spmm)
__device__ float  g_inv   [N_NODES];               // 1/sqrt(deg)
__device__ float  g_inv2  [N_NODES];               // 1/deg
__device__ int    g_part  [N_PART];
__device__ int    g_rowptr[N_NODES + 1];           // +1 sentinel = N_DIR
__device__ int2   g_slot  [N_EDGES];               // per-edge (slot_u, slot_v)
__device__ int    g_adj   [N_DIR];                 // src index only

// ---------------- kernels ---------------------------------------------------

// Degree atomics WITH slot capture (atomicAdd return = slot within row).
// Relies on g_degi == 0 at entry (loader zero-init; layer-1 spmm resets per run).
__global__ void k_deg(const int* __restrict__ eu, const int* __restrict__ ei) {
    int e = blockIdx.x * blockDim.x + threadIdx.x;
    if (e >= N_EDGES) return;
    int u = eu[e];
    int v = NUM_USERS + ei[e];
    int su = atomicAdd(&g_degi[u], 1);
    int sv = atomicAdd(&g_degi[v], 1);
    g_slot[e] = make_int2(su, sv);
}

// per-256-chunk degree partial sums
__global__ void k_part() {
    __shared__ int s[256];
    int t = threadIdx.x;
    int n = blockIdx.x * 256 + t;
    s[t] = (n < N_NODES) ? g_degi[n] : 0;
    __syncthreads();
    for (int off = 128; off > 0; off >>= 1) {
        if (t < off) s[t] += s[t + off];
        __syncthreads();
    }
    if (t == 0) g_part[blockIdx.x] = s[0];
}

// rowptr + inv + inv2: block sums partials before it, then local 256-scan.
__global__ void k_rowptr() {
    __shared__ int s[256];
    __shared__ int base_s;
    int t   = threadIdx.x;
    int bid = blockIdx.x;

    int p = 0;
    for (int i = t; i < bid; i += 256) p += g_part[i];
    s[t] = p;
    __syncthreads();
    for (int off = 128; off > 0; off >>= 1) {
        if (t < off) s[t] += s[t + off];
        __syncthreads();
    }
    if (t == 0) base_s = s[0];
    __syncthreads();
    int base = base_s;

    int n = bid * 256 + t;
    int v = (n < N_NODES) ? g_degi[n] : 0;
    if (n < N_NODES) {
        float fd = (float)v;
        g_inv [n] = (v > 0) ? rsqrtf(fd)  : 0.f;
        g_inv2[n] = (v > 0) ? (1.0f / fd) : 0.f;
    }
    s[t] = v;
    __syncthreads();
    for (int off = 1; off < 256; off <<= 1) {
        int a = (t >= off) ? s[t - off] : 0;
        __syncthreads();
        s[t] += a;
        __syncthreads();
    }
    if (n < N_NODES) {
        g_rowptr[n] = base + s[t] - v;
        if (n == N_NODES - 1) g_rowptr[N_NODES] = N_DIR;
    }
}

// Fused: CSR fill (no atomics — slots precomputed) + inv-prescaled fp16 cast.
// Both depend only on rowptr/inv; cast streaming hides under fill's scattered
// stores. x̃0 = inv[node] * x0[node] makes layer 1 a plain unweighted sum.
__global__ void k_fill_cast(const int* __restrict__ eu, const int* __restrict__ ei,
                            const float* __restrict__ uemb, const float* __restrict__ iemb) {
    int i = blockIdx.x * blockDim.x + threadIdx.x;   // 0 .. 1.2M-1
    const int n8 = TOT_F / 8;                        // 1,200,000
    if (i < n8) {
        int base = i * 8;
        const float4* src = (base < USER_F)
            ? reinterpret_cast<const float4*>(uemb + base)
            : reinterpret_cast<const float4*>(iemb + (base - USER_F));
        float w = g_inv[i >> 3];                     // node = base/64 = i/8
        float4 a = src[0];
        float4 b = src[1];
        uint4 pack;
        __half2* h = reinterpret_cast<__half2*>(&pack);
        h[0] = __floats2half2_rn(w * a.x, w * a.y);
        h[1] = __floats2half2_rn(w * a.z, w * a.w);
        h[2] = __floats2half2_rn(w * b.x, w * b.y);
        h[3] = __floats2half2_rn(w * b.z, w * b.w);
        reinterpret_cast<uint4*>(g_x0h)[i] = pack;
    }
    if (i < N_EDGES) {
        int u = eu[i];
        int v = NUM_USERS + ei[i];
        int2 s = g_slot[i];
        g_adj[g_rowptr[u] + s.x] = v;
        g_adj[g_rowptr[v] + s.y] = u;
    }
}

// SpMM core: y[dst] = inv2[dst] * sum_src x[src]   (fp16 in/out, fp32 acc)
// 4 lanes per row; lane owns 16 halves (two uint4). Neighbor PAIRS summed in
// half2 (1 rounding) before convert+fp32 add: 1 HADD2 + 2 cvt + 2 fadd per
// half2-pair vs 4 cvt + 4 fadd. RESET=1 instance also clears g_degi.
template<int RESET>
__global__ void k_spmm(const __half* __restrict__ x, __half* __restrict__ y) {
    int gid = blockIdx.x * blockDim.x + threadIdx.x;
    if (RESET && gid < N_NODES) g_degi[gid] = 0;     // reset for next replay
    int row = gid >> 2;
    int sub = gid & 3;
    if (row >= N_NODES) return;

    int beg = g_rowptr[row];
    int cnt = g_rowptr[row + 1] - beg;

    float acc[16];
    #pragma unroll
    for (int q = 0; q < 16; q++) acc[q] = 0.f;

    int j = 0;
    for (; j + 1 < cnt; j += 2) {
        int s0 = g_adj[beg + j];
        int s1 = g_adj[beg + j + 1];
        const uint4* p0 = reinterpret_cast<const uint4*>(x + (size_t)s0 * LATENT) + 2 * sub;
        const uint4* p1 = reinterpret_cast<const uint4*>(x + (size_t)s1 * LATENT) + 2 * sub;
        uint4 a0 = p0[0]; uint4 a1 = p0[1];
        uint4 b0 = p1[0]; uint4 b1 = p1[1];

        const __half2* A0 = reinterpret_cast<const __half2*>(&a0);
        const __half2* B0 = reinterpret_cast<const __half2*>(&b0);
        #pragma unroll
        for (int q = 0; q < 4; q++) {
            __half2 s = __hadd2(A0[q], B0[q]);       // pairwise fp16 sum (1 rounding)
            float2 f = __half22float2(s);
            acc[2 * q]     += f.x;
            acc[2 * q + 1] += f.y;
        }
        const __half2* A1 = reinterpret_cast<const __half2*>(&a1);
        const __half2* B1 = reinterpret_cast<const __half2*>(&b1);
        #pragma unroll
        for (int q = 0; q < 4; q++) {
            __half2 s = __hadd2(A1[q], B1[q]);
            float2 f = __half22float2(s);
            acc[8 + 2 * q]     += f.x;
            acc[8 + 2 * q + 1] += f.y;
        }
    }
    if (j < cnt) {                                   // odd leftover, no pairing
        int s0 = g_adj[beg + j];
        const uint4* p0 = reinterpret_cast<const uint4*>(x + (size_t)s0 * LATENT) + 2 * sub;
        uint4 a0 = p0[0]; uint4 a1 = p0[1];
        const __half2* A0 = reinterpret_cast<const __half2*>(&a0);
        #pragma unroll
        for (int q = 0; q < 4; q++) {
            float2 f = __half22float2(A0[q]);
            acc[2 * q]     += f.x;
            acc[2 * q + 1] += f.y;
        }
        const __half2* A1 = reinterpret_cast<const __half2*>(&a1);
        #pragma unroll
        for (int q = 0; q < 4; q++) {
            float2 f = __half22float2(A1[q]);
            acc[8 + 2 * q]     += f.x;
            acc[8 + 2 * q + 1] += f.y;
        }
    }

    float s = g_inv2[row];
    uint4 o0, o1;
    __half2* h0 = reinterpret_cast<__half2*>(&o0);
    __half2* h1 = reinterpret_cast<__half2*>(&o1);
    #pragma unroll
    for (int q = 0; q < 4; q++) {
        h0[q] = __floats2half2_rn(acc[2 * q] * s,     acc[2 * q + 1] * s);
        h1[q] = __floats2half2_rn(acc[8 + 2 * q] * s, acc[8 + 2 * q + 1] * s);
    }
    uint4* yp = reinterpret_cast<uint4*>(y + (size_t)row * LATENT) + 2 * sub;
    yp[0] = o0;
    yp[1] = o1;
}

// Fused layer-4 + final dot. One 64-thread block per batch pair.
__global__ void k_final(const int* __restrict__ users, const int* __restrict__ items,
                        const float* __restrict__ uemb, const float* __restrict__ iemb,
                        const __half* __restrict__ z1, const __half* __restrict__ z2,
                        const __half* __restrict__ z3,
                        float* __restrict__ out) {
    __shared__ float red[2];
    int b = blockIdx.x;
    int t = threadIdx.x;            // 0..63 = column

    int u  = users[b];
    int it = NUM_USERS + items[b];

    int bu = g_rowptr[u];
    int cu = g_rowptr[u + 1] - bu;
    int bi = g_rowptr[it];
    int ci = g_rowptr[it + 1] - bi;

    float z4u = 0.f;
    for (int j = 0; j < cu; j++) {
        int s = g_adj[bu + j];
        z4u += __half2float(z3[(size_t)s * LATENT + t]);
    }
    z4u *= g_inv2[u];
    size_t ou = (size_t)u * LATENT + t;
    float zu = __half2float(z1[ou]) + __half2float(z2[ou]) + __half2float(z3[ou]) + z4u;
    float su = uemb[ou] + sqrtf((float)cu) * zu;

    float z4i = 0.f;
    for (int j = 0; j < ci; j++) {
        int s = g_adj[bi + j];
        z4i += __half2float(z3[(size_t)s * LATENT + t]);
    }
    z4i *= g_inv2[it];
    size_t oi = (size_t)it * LATENT + t;
    float zi = __half2float(z1[oi]) + __half2float(z2[oi]) + __half2float(z3[oi]) + z4i;
    float si = iemb[(size_t)(it - NUM_USERS) * LATENT + t] + sqrtf((float)ci) * zi;

    float dot = su * si;
    #pragma unroll
    for (int off = 16; off > 0; off >>= 1)
        dot += __shfl_xor_sync(0xffffffffu, dot, off);
    if ((t & 31) == 0) red[t >> 5] = dot;
    __syncthreads();
    if (t == 0) out[b] = (red[0] + red[1]) * (1.0f / 25.0f);
}

// ---------------- launch ----------------------------------------------------
extern "C" void kernel_launch(void* const* d_in, const int* in_sizes, int n_in,
                              void* d_out, int out_size) {
    const int*   users = (const int*)  d_in[0];
    const int*   items = (const int*)  d_in[1];
    const int*   eu    = (const int*)  d_in[2];
    const int*   ei    = (const int*)  d_in[3];
    const float* uemb  = (const float*)d_in[4];
    const float* iemb  = (const float*)d_in[5];
    float*       out   = (float*)d_out;

    const int T = 256;
    const int n8     = TOT_F / 8;                    // 1.2M
    const int gBig   = (n8 + T - 1) / T;
    const int gEdge  = (N_EDGES + T - 1) / T;
    const int gRow4  = (N_NODES * 4 + T - 1) / T;

    static __half* pZ = nullptr; static __half* pX = nullptr;
    if (!pZ) { cudaGetSymbolAddress((void**)&pZ, g_z);
               cudaGetSymbolAddress((void**)&pX, g_x0h); }
    __half* z1 = pZ;
    __half* z2 = pZ + (size_t)TOT_F;
    __half* z3 = pZ + (size_t)2 * TOT_F;

    // CSR build; cast (inv-prescaled) fused with fill
    k_deg      <<<gEdge, T>>>(eu, ei);
    k_part     <<<N_PART, 256>>>();
    k_rowptr   <<<N_PART, 256>>>();
    k_fill_cast<<<gBig, T>>>(eu, ei, uemb, iemb);

    // layers 1..3: identical plain sums (layer 1 input is inv-prescaled x0)
    k_spmm<1><<<gRow4, T>>>(pX, z1);
    k_spmm<0><<<gRow4, T>>>(z1, z2);
    k_spmm<0><<<gRow4, T>>>(z2, z3);

    // layer 4 fused into final (only batch rows needed)
    k_final<<<BATCH, 64>>>(users, items, uemb, iemb, z1, z2, z3, out);
}

// round 15
// speedup vs baseline: 1.4774x; 1.4774x over previous
#include <cuda_runtime.h>
#include <cuda_bf16.h>
#include <cuda_fp16.h>
#include <cstdint>

#define NUM_USERS 100000
#define NUM_ITEMS 50000
#define LATENT    64
#define N_EDGES   600000
#define BATCH     4096
#define N_NODES   (NUM_USERS + NUM_ITEMS)          // 150000
#define TOT_F     (N_NODES * LATENT)               // 9,600,000
#define USER_F    (NUM_USERS * LATENT)
#define N_DIR     (2 * N_EDGES)
#define N_PART    ((N_NODES + 255) / 256)          // 586

// ---------------- scratch (device globals) ----------------------------------
__device__ __half g_x0h[TOT_F];                    // fp16 x0 (19.2 MB)
__device__ __half g_z[3 * TOT_F];                  // z_1..z_3 fp16 (57.6 MB)
__device__ int    g_degi  [N_NODES];               // zero at entry (reset by spmm1h)
__device__ float  g_inv   [N_NODES];               // 1/sqrt(deg)
__device__ float  g_inv2  [N_NODES];               // 1/deg
__device__ int    g_part  [N_PART];
__device__ int    g_rowptr[N_NODES + 1];           // +1 sentinel = N_DIR
__device__ int2   g_slot  [N_EDGES];               // per-edge (slot_u, slot_v)
__device__ int    g_adj   [N_DIR];                 // src index only

// ---------------- kernels ---------------------------------------------------

// Fused: degree atomics WITH slot capture + fp16 cast of x0 (R10 structure).
// Relies on g_degi == 0 at entry (loader zero-init; k_spmm1h resets per run).
__global__ void k_deg_conv(const int* __restrict__ eu, const int* __restrict__ ei,
                           const float* __restrict__ uemb, const float* __restrict__ iemb) {
    int i = blockIdx.x * blockDim.x + threadIdx.x;   // 0 .. 1.2M-1
    const int n8 = TOT_F / 8;                        // 1,200,000
    if (i < n8) {
        int base = i * 8;
        const float4* src = (base < USER_F)
            ? reinterpret_cast<const float4*>(uemb + base)
            : reinterpret_cast<const float4*>(iemb + (base - USER_F));
        float4 a = src[0];
        float4 b = src[1];
        uint4 pack;
        __half2* h = reinterpret_cast<__half2*>(&pack);
        h[0] = __floats2half2_rn(a.x, a.y);
        h[1] = __floats2half2_rn(a.z, a.w);
        h[2] = __floats2half2_rn(b.x, b.y);
        h[3] = __floats2half2_rn(b.z, b.w);
        reinterpret_cast<uint4*>(g_x0h)[i] = pack;
    }
    if (i < N_EDGES) {
        int u = eu[i];
        int v = NUM_USERS + ei[i];
        int su = atomicAdd(&g_degi[u], 1);
        int sv = atomicAdd(&g_degi[v], 1);
        g_slot[i] = make_int2(su, sv);
    }
}

// per-256-chunk degree partial sums
__global__ void k_part() {
    __shared__ int s[256];
    int t = threadIdx.x;
    int n = blockIdx.x * 256 + t;
    s[t] = (n < N_NODES) ? g_degi[n] : 0;
    __syncthreads();
    for (int off = 128; off > 0; off >>= 1) {
        if (t < off) s[t] += s[t + off];
        __syncthreads();
    }
    if (t == 0) g_part[blockIdx.x] = s[0];
}

// rowptr + inv + inv2: block sums partials before it, then local 256-scan.
__global__ void k_rowptr() {
    __shared__ int s[256];
    __shared__ int base_s;
    int t   = threadIdx.x;
    int bid = blockIdx.x;

    int p = 0;
    for (int i = t; i < bid; i += 256) p += g_part[i];
    s[t] = p;
    __syncthreads();
    for (int off = 128; off > 0; off >>= 1) {
        if (t < off) s[t] += s[t + off];
        __syncthreads();
    }
    if (t == 0) base_s = s[0];
    __syncthreads();
    int base = base_s;

    int n = bid * 256 + t;
    int v = (n < N_NODES) ? g_degi[n] : 0;
    if (n < N_NODES) {
        float fd = (float)v;
        g_inv [n] = (v > 0) ? rsqrtf(fd)  : 0.f;
        g_inv2[n] = (v > 0) ? (1.0f / fd) : 0.f;
    }
    s[t] = v;
    __syncthreads();
    for (int off = 1; off < 256; off <<= 1) {
        int a = (t >= off) ? s[t - off] : 0;
        __syncthreads();
        s[t] += a;
        __syncthreads();
    }
    if (n < N_NODES) {
        g_rowptr[n] = base + s[t] - v;
        if (n == N_NODES - 1) g_rowptr[N_NODES] = N_DIR;
    }
}

// CSR fill: NO atomics — slots were captured during degree counting.
__global__ void k_fill(const int* __restrict__ eu, const int* __restrict__ ei) {
    int e = blockIdx.x * blockDim.x + threadIdx.x;
    if (e >= N_EDGES) return;
    int u = eu[e];
    int v = NUM_USERS + ei[e];
    int2 s = g_slot[e];
    g_adj[g_rowptr[u] + s.x] = v;
    g_adj[g_rowptr[v] + s.y] = u;
}

// Layer 1: z1[dst] = inv2[dst] * sum_src inv[src] * x0h[src]
// 8 lanes per row; lane owns 8 halves (uint4). fp32 accumulation.
// Also resets g_degi for the next graph replay. (R10 verbatim.)
__global__ void k_spmm1h(const __half* __restrict__ x, __half* __restrict__ y) {
    int gid = blockIdx.x * blockDim.x + threadIdx.x;
    if (gid < N_NODES) g_degi[gid] = 0;              // reset for next replay
    int row = gid >> 3;
    int sub = gid & 7;
    if (row >= N_NODES) return;

    int beg = g_rowptr[row];
    int cnt = g_rowptr[row + 1] - beg;
    float acc[8] = {0.f, 0.f, 0.f, 0.f, 0.f, 0.f, 0.f, 0.f};

    auto accum = [&](uint4 v, float ws) {
        const __half2* h = reinterpret_cast<const __half2*>(&v);
        #pragma unroll
        for (int q = 0; q < 4; q++) {
            float2 f = __half22float2(h[q]);
            acc[2 * q]     += ws * f.x;
            acc[2 * q + 1] += ws * f.y;
        }
    };

    int j = 0;
    for (; j + 1 < cnt; j += 2) {
        int s0 = g_adj[beg + j + 0];
        int s1 = g_adj[beg + j + 1];
        float w0 = g_inv[s0];
        float w1 = g_inv[s1];
        uint4 v0 = reinterpret_cast<const uint4*>(x + (size_t)s0 * LATENT)[sub];
        uint4 v1 = reinterpret_cast<const uint4*>(x + (size_t)s1 * LATENT)[sub];
        accum(v0, w0); accum(v1, w1);
    }
    if (j < cnt) {
        int s0 = g_adj[beg + j];
        float w0 = g_inv[s0];
        uint4 v0 = reinterpret_cast<const uint4*>(x + (size_t)s0 * LATENT)[sub];
        accum(v0, w0);
    }

    float s = g_inv2[row];
    uint4 outp;
    __half2* oh = reinterpret_cast<__half2*>(&outp);
    #pragma unroll
    for (int q = 0; q < 4; q++)
        oh[q] = __floats2half2_rn(acc[2 * q] * s, acc[2 * q + 1] * s);
    reinterpret_cast<uint4*>(y + (size_t)row * LATENT)[sub] = outp;
}

// Layers 2..3: z_{l+1}[dst] = inv2[dst] * sum_src z_l[src]   (fp16 in/out)
// ONLY change vs R10: neighbor PAIRS are summed with __hadd2 before fp32
// conversion — 4 HADD2 + 8 cvt + 8 FADD per pair vs 16 cvt + 16 FADD.
__global__ void k_spmmN(const __half* __restrict__ x, __half* __restrict__ y) {
    int gid = blockIdx.x * blockDim.x + threadIdx.x;
    int row = gid >> 3;
    int sub = gid & 7;
    if (row >= N_NODES) return;

    int beg = g_rowptr[row];
    int cnt = g_rowptr[row + 1] - beg;
    float acc[8] = {0.f, 0.f, 0.f, 0.f, 0.f, 0.f, 0.f, 0.f};

    int j = 0;
    for (; j + 3 < cnt; j += 4) {                    // 4 neighbors, 2 hadd2-pairs
        int s0 = g_adj[beg + j + 0];
        int s1 = g_adj[beg + j + 1];
        int s2 = g_adj[beg + j + 2];
        int s3 = g_adj[beg + j + 3];
        uint4 v0 = reinterpret_cast<const uint4*>(x + (size_t)s0 * LATENT)[sub];
        uint4 v1 = reinterpret_cast<const uint4*>(x + (size_t)s1 * LATENT)[sub];
        uint4 v2 = reinterpret_cast<const uint4*>(x + (size_t)s2 * LATENT)[sub];
        uint4 v3 = reinterpret_cast<const uint4*>(x + (size_t)s3 * LATENT)[sub];
        const __half2* A = reinterpret_cast<const __half2*>(&v0);
        const __half2* B = reinterpret_cast<const __half2*>(&v1);
        const __half2* C = reinterpret_cast<const __half2*>(&v2);
        const __half2* D = reinterpret_cast<const __half2*>(&v3);
        #pragma unroll
        for (int q = 0; q < 4; q++) {
            __half2 sAB = __hadd2(A[q], B[q]);       // 1 fp16 rounding per pair
            __half2 sCD = __hadd2(C[q], D[q]);
            float2 f0 = __half22float2(sAB);
            float2 f1 = __half22float2(sCD);
            acc[2 * q]     += f0.x + f1.x;
            acc[2 * q + 1] += f0.y + f1.y;
        }
    }
    for (; j + 1 < cnt; j += 2) {
        int s0 = g_adj[beg + j + 0];
        int s1 = g_adj[beg + j + 1];
        uint4 v0 = reinterpret_cast<const uint4*>(x + (size_t)s0 * LATENT)[sub];
        uint4 v1 = reinterpret_cast<const uint4*>(x + (size_t)s1 * LATENT)[sub];
        const __half2* A = reinterpret_cast<const __half2*>(&v0);
        const __half2* B = reinterpret_cast<const __half2*>(&v1);
        #pragma unroll
        for (int q = 0; q < 4; q++) {
            __half2 sAB = __hadd2(A[q], B[q]);
            float2 f = __half22float2(sAB);
            acc[2 * q]     += f.x;
            acc[2 * q + 1] += f.y;
        }
    }
    if (j < cnt) {
        int s0 = g_adj[beg + j];
        uint4 v0 = reinterpret_cast<const uint4*>(x + (size_t)s0 * LATENT)[sub];
        const __half2* A = reinterpret_cast<const __half2*>(&v0);
        #pragma unroll
        for (int q = 0; q < 4; q++) {
            float2 f = __half22float2(A[q]);
            acc[2 * q]     += f.x;
            acc[2 * q + 1] += f.y;
        }
    }

    float s = g_inv2[row];
    uint4 outp;
    __half2* oh = reinterpret_cast<__half2*>(&outp);
    #pragma unroll
    for (int q = 0; q < 4; q++)
        oh[q] = __floats2half2_rn(acc[2 * q] * s, acc[2 * q + 1] * s);
    reinterpret_cast<uint4*>(y + (size_t)row * LATENT)[sub] = outp;
}

// Fused layer-4 + final dot. One 64-thread block per batch pair. (R10 verbatim.)
__global__ void k_final(const int* __restrict__ users, const int* __restrict__ items,
                        const float* __restrict__ uemb, const float* __restrict__ iemb,
                        const __half* __restrict__ z1, const __half* __restrict__ z2,
                        const __half* __restrict__ z3,
                        float* __restrict__ out) {
    __shared__ float red[2];
    int b = blockIdx.x;
    int t = threadIdx.x;            // 0..63 = column

    int u  = users[b];
    int it = NUM_USERS + items[b];

    int bu = g_rowptr[u];
    int cu = g_rowptr[u + 1] - bu;
    int bi = g_rowptr[it];
    int ci = g_rowptr[it + 1] - bi;

    float z4u = 0.f;
    for (int j = 0; j < cu; j++) {
        int s = g_adj[bu + j];
        z4u += __half2float(z3[(size_t)s * LATENT + t]);
    }
    z4u *= g_inv2[u];
    size_t ou = (size_t)u * LATENT + t;
    float zu = __half2float(z1[ou]) + __half2float(z2[ou]) + __half2float(z3[ou]) + z4u;
    float su = uemb[ou] + sqrtf((float)cu) * zu;

    float z4i = 0.f;
    for (int j = 0; j < ci; j++) {
        int s = g_adj[bi + j];
        z4i += __half2float(z3[(size_t)s * LATENT + t]);
    }
    z4i *= g_inv2[it];
    size_t oi = (size_t)it * LATENT + t;
    float zi = __half2float(z1[oi]) + __half2float(z2[oi]) + __half2float(z3[oi]) + z4i;
    float si = iemb[(size_t)(it - NUM_USERS) * LATENT + t] + sqrtf((float)ci) * zi;

    float dot = su * si;
    #pragma unroll
    for (int off = 16; off > 0; off >>= 1)
        dot += __shfl_xor_sync(0xffffffffu, dot, off);
    if ((t & 31) == 0) red[t >> 5] = dot;
    __syncthreads();
    if (t == 0) out[b] = (red[0] + red[1]) * (1.0f / 25.0f);
}

// ---------------- launch ----------------------------------------------------
extern "C" void kernel_launch(void* const* d_in, const int* in_sizes, int n_in,
                              void* d_out, int out_size) {
    const int*   users = (const int*)  d_in[0];
    const int*   items = (const int*)  d_in[1];
    const int*   eu    = (const int*)  d_in[2];
    const int*   ei    = (const int*)  d_in[3];
    const float* uemb  = (const float*)d_in[4];
    const float* iemb  = (const float*)d_in[5];
    float*       out   = (float*)d_out;

    const int T = 256;
    const int n8     = TOT_F / 8;                    // 1.2M
    const int gBig   = (n8 + T - 1) / T;
    const int gEdge  = (N_EDGES + T - 1) / T;
    const int gRow8  = (N_NODES * 8 + T - 1) / T;

    static __half* pZ = nullptr; static __half* pX = nullptr;
    if (!pZ) { cudaGetSymbolAddress((void**)&pZ, g_z);
               cudaGetSymbolAddress((void**)&pX, g_x0h); }
    __half* z1 = pZ;
    __half* z2 = pZ + (size_t)TOT_F;
    __half* z3 = pZ + (size_t)2 * TOT_F;

    // setup: deg atomics (slot capture) + fp16 cast fused, then CSR build
    k_deg_conv<<<gBig, T>>>(eu, ei, uemb, iemb);
    k_part    <<<N_PART, 256>>>();
    k_rowptr  <<<N_PART, 256>>>();
    k_fill    <<<gEdge, T>>>(eu, ei);

    // layers 1..3 materialized (fp16 storage, fp32 accumulation)
    k_spmm1h<<<gRow8, T>>>(pX, z1);
    k_spmmN <<<gRow8, T>>>(z1, z2);
    k_spmmN <<<gRow8, T>>>(z2, z3);

    // layer 4 fused into final (only batch rows needed)
    k_final<<<BATCH, 64>>>(users, items, uemb, iemb, z1, z2, z3, out);
}